// round 4
// baseline (speedup 1.0000x reference)
#include <cuda_runtime.h>
#include <cstdint>

#define VOCAB 50000
#define DIM   768
#define NTOK  16384
#define BM    128
#define BN    128
#define BK    16
#define NCHUNK (DIM / BK)     // 48
#define AS_STRIDE 20          // 16 + 4 pad  -> conflict-free fragment LDS
#define BS_STRIDE 136         // 128 + 8 pad -> conflict-free fragment LDS

__device__ int g_cnt;
__device__ int g_tok64;               // 1 if token buffer is int64, 0 if int32
__device__ int g_list[NTOK];          // token position (row in output)
__device__ int g_tok[NTOK];           // token id (row in embedding table)
__device__ uint32_t Wt[DIM * DIM];    // W pre-converted to tf32 (RNA)
__device__ uint32_t At[NTOK * DIM];   // gathered+converted A rows (zero-padded to BM)

// ---------------------------------------------------------------- utilities
__device__ __forceinline__ uint32_t f2tf32(float x) {
    uint32_t r;
    asm("cvt.rna.tf32.f32 %0, %1;" : "=r"(r) : "f"(x));
    return r;
}

__device__ __forceinline__ void cp16(uint32_t smem_dst, const void* gsrc) {
    asm volatile("cp.async.cg.shared.global [%0], [%1], 16;\n"
                 :: "r"(smem_dst), "l"(gsrc));
}

__device__ __forceinline__ void mma_tf32(float c[4], const uint32_t a[4], const uint32_t b[2]) {
    asm volatile(
        "mma.sync.aligned.m16n8k8.row.col.f32.tf32.tf32.f32 "
        "{%0,%1,%2,%3}, {%4,%5,%6,%7}, {%8,%9}, {%0,%1,%2,%3};\n"
        : "+f"(c[0]), "+f"(c[1]), "+f"(c[2]), "+f"(c[3])
        : "r"(a[0]), "r"(a[1]), "r"(a[2]), "r"(a[3]), "r"(b[0]), "r"(b[1]));
}

// ---------------------------------------------------------------- small kernels
// Detect token dtype from data: int64 tokens in [0,50000) have all-zero hi words.
__global__ void k_detect_reset(const int* __restrict__ words) {
    int is64 = 1;
    #pragma unroll 1
    for (int i = 1; i < 256; i += 2) {
        if (words[i] != 0) { is64 = 0; break; }
    }
    g_tok64 = is64;
    g_cnt = 0;
}

__device__ __forceinline__ int load_token(const int* __restrict__ t32, int p, int is64) {
    return is64 ? t32[2 * p] : t32[p];
}

__global__ void k_compact(const int* __restrict__ token,
                          const int* __restrict__ need) {
    int p = blockIdx.x * blockDim.x + threadIdx.x;
    if (p < NTOK) {
        int t = load_token(token, p, g_tok64);
        if (t >= 0 && t < VOCAB && need[t]) {
            int pos = atomicAdd(&g_cnt, 1);
            g_list[pos] = p;
            g_tok[pos]  = t;
        }
    }
}

// W -> tf32 (one element quad per thread)
__global__ void k_wconv(const float* __restrict__ W) {
    int i = (blockIdx.x * blockDim.x + threadIdx.x) * 4;
    float4 v = *(const float4*)(W + i);
    uint4 o;
    o.x = f2tf32(v.x); o.y = f2tf32(v.y); o.z = f2tf32(v.z); o.w = f2tf32(v.w);
    *(uint4*)(Wt + i) = o;
}

// Gather + convert compacted A rows into At; zero-pad to the next BM boundary.
__global__ void k_aconv(const float* __restrict__ emb) {
    const int r = blockIdx.x;
    const int cnt = g_cnt;
    const int cnt_pad = (cnt + BM - 1) & ~(BM - 1);
    if (r >= cnt_pad) return;
    uint32_t* dst = At + (size_t)r * DIM;
    const int i = threadIdx.x * 4;     // 192 threads * 4 floats = 768
    if (r < cnt) {
        const float* src = emb + (size_t)g_tok[r] * DIM;
        float4 v = *(const float4*)(src + i);
        uint4 o;
        o.x = f2tf32(v.x); o.y = f2tf32(v.y); o.z = f2tf32(v.z); o.w = f2tf32(v.w);
        *(uint4*)(dst + i) = o;
    } else {
        *(uint4*)(dst + i) = make_uint4(0, 0, 0, 0);
    }
}

// One block per token; copy embedding row for tokens that do NOT need mapping.
__global__ void k_copy(const int* __restrict__ token,
                       const int* __restrict__ need,
                       const float4* __restrict__ emb,
                       float4* __restrict__ out) {
    int p = blockIdx.x;
    int t = load_token(token, p, g_tok64);
    if (t < 0 || t >= VOCAB) return;
    if (need[t]) return;               // GEMM writes these rows
    const float4* src = emb + (size_t)t * (DIM / 4);
    float4*       dst = out + (size_t)p * (DIM / 4);
    dst[threadIdx.x] = src[threadIdx.x];  // blockDim.x == 192
}

// ---------------------------------------------------------------- GEMM
// out[g_list[r]] = At[r] @ Wt + bias, over r < g_cnt (A pre-converted/padded).
// 2-stage cp.async pipeline, 8 warps (2x4), warp tile 64x32, thread tile 4x4 mma.
__global__ __launch_bounds__(256, 2) void k_gemm(
    const float* __restrict__ bias, float* __restrict__ out)
{
    const int cnt = g_cnt;
    const int mtile = blockIdx.y;
    if (mtile * BM >= cnt) return;
    const int n0 = blockIdx.x * BN;

    __shared__ uint32_t As[2][BM][AS_STRIDE];
    __shared__ uint32_t Bs[2][BK][BS_STRIDE];

    const int tid  = threadIdx.x;
    const int lane = tid & 31;
    const int wid  = tid >> 5;
    const int warp_m = (wid >> 2) * 64;   // 2 warps in M
    const int warp_n = (wid & 3) * 32;    // 4 warps in N

    // A cp.async mapping: row = tid>>1, two float4 at cols (tid&1)*8 + {0,4}
    const int arow = tid >> 1;
    const int acol = (tid & 1) * 8;
    const uint32_t* agp = At + (size_t)(mtile * BM + arow) * DIM + acol;

    // B cp.async mapping: row = tid>>4, two float4 at cols (tid&15)*8 + {0,4}
    const int brow = tid >> 4;
    const int bcol = (tid & 15) * 8;
    const uint32_t* bgp = Wt + (size_t)brow * DIM + n0 + bcol;

    float acc[4][4][4];
    #pragma unroll
    for (int i = 0; i < 4; i++)
        #pragma unroll
        for (int j = 0; j < 4; j++)
            #pragma unroll
            for (int r = 0; r < 4; r++) acc[i][j][r] = 0.0f;

    // stage-issue helper (manually inlined twice below)
    #define ISSUE_CHUNK(chunk, s)                                              \
    {                                                                          \
        uint32_t asm0 = (uint32_t)__cvta_generic_to_shared(&As[s][arow][acol]);\
        cp16(asm0,      agp + (chunk) * BK);                                   \
        cp16(asm0 + 16, agp + (chunk) * BK + 4);                               \
        uint32_t bsm0 = (uint32_t)__cvta_generic_to_shared(&Bs[s][brow][bcol]);\
        cp16(bsm0,      bgp + (size_t)(chunk) * BK * DIM);                     \
        cp16(bsm0 + 16, bgp + (size_t)(chunk) * BK * DIM + 4);                 \
        asm volatile("cp.async.commit_group;\n" ::: "memory");                 \
    }

    ISSUE_CHUNK(0, 0)

    for (int chunk = 0; chunk < NCHUNK; chunk++) {
        asm volatile("cp.async.wait_group 0;\n" ::: "memory");
        __syncthreads();   // chunk data ready; all warps done with other stage

        if (chunk + 1 < NCHUNK) ISSUE_CHUNK(chunk + 1, (chunk + 1) & 1)

        const int s = chunk & 1;
        #pragma unroll
        for (int ks = 0; ks < 2; ks++) {
            uint32_t afr[4][4], bfr[4][2];
            const int k = ks * 8 + (lane & 3);
            #pragma unroll
            for (int fm = 0; fm < 4; fm++) {
                const int m0 = warp_m + fm * 16 + (lane >> 2);
                afr[fm][0] = As[s][m0][k];
                afr[fm][1] = As[s][m0 + 8][k];
                afr[fm][2] = As[s][m0][k + 4];
                afr[fm][3] = As[s][m0 + 8][k + 4];
            }
            #pragma unroll
            for (int fn = 0; fn < 4; fn++) {
                const int nn = warp_n + fn * 8 + (lane >> 2);
                bfr[fn][0] = Bs[s][k][nn];
                bfr[fn][1] = Bs[s][k + 4][nn];
            }
            #pragma unroll
            for (int fm = 0; fm < 4; fm++)
                #pragma unroll
                for (int fn = 0; fn < 4; fn++)
                    mma_tf32(acc[fm][fn], afr[fm], bfr[fn]);
        }
    }
    #undef ISSUE_CHUNK

    // epilogue: bias + scatter to out rows
    #pragma unroll
    for (int fm = 0; fm < 4; fm++) {
        const int r0 = mtile * BM + warp_m + fm * 16 + (lane >> 2);
        const int r1 = r0 + 8;
        #pragma unroll
        for (int fn = 0; fn < 4; fn++) {
            const int col = n0 + warp_n + fn * 8 + 2 * (lane & 3);
            const float b0 = bias[col], b1 = bias[col + 1];
            if (r0 < cnt) {
                const int p = g_list[r0];
                float2 v = make_float2(acc[fm][fn][0] + b0, acc[fm][fn][1] + b1);
                *(float2*)&out[(size_t)p * DIM + col] = v;
            }
            if (r1 < cnt) {
                const int p = g_list[r1];
                float2 v = make_float2(acc[fm][fn][2] + b0, acc[fm][fn][3] + b1);
                *(float2*)&out[(size_t)p * DIM + col] = v;
            }
        }
    }
}

// ---------------------------------------------------------------- launch
extern "C" void kernel_launch(void* const* d_in, const int* in_sizes, int n_in,
                              void* d_out, int out_size) {
    const int*   token = (const int*)d_in[0];   // int32 or int64 (auto-detected)
    const int*   need  = (const int*)d_in[1];
    const float* emb   = (const float*)d_in[2];
    const float* W     = (const float*)d_in[3];
    const float* bias  = (const float*)d_in[4];
    float*       out   = (float*)d_out;

    k_detect_reset<<<1, 1>>>(token);
    k_wconv<<<(DIM * DIM / 4) / 256, 256>>>(W);
    k_compact<<<(NTOK + 255) / 256, 256>>>(token, need);
    k_copy<<<NTOK, DIM / 4>>>(token, need, (const float4*)emb, (float4*)out);
    k_aconv<<<NTOK, DIM / 4>>>(emb);
    k_gemm<<<dim3(DIM / BN, NTOK / BM), 256>>>(bias, out);
}

// round 5
// speedup vs baseline: 1.0146x; 1.0146x over previous
#include <cuda_runtime.h>
#include <cstdint>

#define VOCAB 50000
#define DIM   768
#define NTOK  16384
#define BM    128
#define BN    64
#define BK    16
#define NCHUNK (DIM / BK)     // 48
#define AS_STRIDE 20          // 16 + 4 pad  -> conflict-free fragment LDS
#define BS_STRIDE 72          // 64 + 8 pad  -> conflict-free fragment LDS

__device__ int g_cnt;
__device__ int g_tok64;               // 1 if token buffer is int64, 0 if int32
__device__ int g_list[NTOK];          // token position (row in output)
__device__ int g_tok[NTOK];           // token id (row in embedding table)

// ---------------------------------------------------------------- utilities
__device__ __forceinline__ uint32_t f2tf32(float x) {
    uint32_t r;
    asm("cvt.rna.tf32.f32 %0, %1;" : "=r"(r) : "f"(x));
    return r;
}

__device__ __forceinline__ void cp16(uint32_t smem_dst, const void* gsrc) {
    asm volatile("cp.async.cg.shared.global [%0], [%1], 16;\n"
                 :: "r"(smem_dst), "l"(gsrc));
}

__device__ __forceinline__ void mma_tf32(float c[4], const uint32_t a[4], const uint32_t b[2]) {
    asm volatile(
        "mma.sync.aligned.m16n8k8.row.col.f32.tf32.tf32.f32 "
        "{%0,%1,%2,%3}, {%4,%5,%6,%7}, {%8,%9}, {%0,%1,%2,%3};\n"
        : "+f"(c[0]), "+f"(c[1]), "+f"(c[2]), "+f"(c[3])
        : "r"(a[0]), "r"(a[1]), "r"(a[2]), "r"(a[3]), "r"(b[0]), "r"(b[1]));
}

// ---------------------------------------------------------------- small kernels
// Detect token dtype from data: int64 tokens in [0,50000) have all-zero hi words.
__global__ void k_detect_reset(const int* __restrict__ words) {
    int is64 = 1;
    #pragma unroll 1
    for (int i = 1; i < 256; i += 2) {
        if (words[i] != 0) { is64 = 0; break; }
    }
    g_tok64 = is64;
    g_cnt = 0;
}

__device__ __forceinline__ int load_token(const int* __restrict__ t32, int p, int is64) {
    return is64 ? t32[2 * p] : t32[p];
}

__global__ void k_compact(const int* __restrict__ token,
                          const int* __restrict__ need) {
    int p = blockIdx.x * blockDim.x + threadIdx.x;
    if (p < NTOK) {
        int t = load_token(token, p, g_tok64);
        if (t >= 0 && t < VOCAB && need[t]) {
            int pos = atomicAdd(&g_cnt, 1);
            g_list[pos] = p;
            g_tok[pos]  = t;
        }
    }
}

// One block per token; copy embedding row for tokens that do NOT need mapping.
__global__ void k_copy(const int* __restrict__ token,
                       const int* __restrict__ need,
                       const float4* __restrict__ emb,
                       float4* __restrict__ out) {
    int p = blockIdx.x;
    int t = load_token(token, p, g_tok64);
    if (t < 0 || t >= VOCAB) return;
    if (need[t]) return;               // GEMM writes these rows
    const float4* src = emb + (size_t)t * (DIM / 4);
    float4*       dst = out + (size_t)p * (DIM / 4);
    dst[threadIdx.x] = src[threadIdx.x];  // blockDim.x == 192
}

// ---------------------------------------------------------------- GEMM
// out[g_list[r]] = emb[g_tok[r]] @ W + bias, r < g_cnt.
// CTA tile 128x64, 8 warps (4x2), warp tile 32x32 -> acc 32 regs.
// 2-stage cp.async pipeline staging raw fp32; tf32 cvt at fragment load.
__global__ __launch_bounds__(256, 2) void k_gemm(
    const float* __restrict__ emb, const float* __restrict__ W,
    const float* __restrict__ bias, float* __restrict__ out)
{
    const int cnt = g_cnt;
    const int mtile = blockIdx.y;
    if (mtile * BM >= cnt) return;
    const int n0 = blockIdx.x * BN;

    __shared__ float As[2][BM][AS_STRIDE];
    __shared__ float Bs[2][BK][BS_STRIDE];

    const int tid  = threadIdx.x;
    const int lane = tid & 31;
    const int wid  = tid >> 5;
    const int warp_m = (wid >> 1) * 32;   // 4 warps in M
    const int warp_n = (wid & 1) * 32;    // 2 warps in N

    // A cp.async mapping: row = tid>>1, two float4 at cols (tid&1)*8 + {0,4}
    const int arow = tid >> 1;
    const int acol = (tid & 1) * 8;
    const int gr   = mtile * BM + arow;
    const int atok = (gr < cnt) ? g_tok[gr] : 0;   // pad rows read row 0 (masked later)
    const float* agp = emb + (size_t)atok * DIM + acol;

    // B cp.async mapping: row = tid>>4, one float4 at col (tid&15)*4
    const int brow = tid >> 4;
    const int bcol = (tid & 15) * 4;
    const float* bgp = W + (size_t)brow * DIM + n0 + bcol;

    float acc[2][4][4];
    #pragma unroll
    for (int i = 0; i < 2; i++)
        #pragma unroll
        for (int j = 0; j < 4; j++)
            #pragma unroll
            for (int r = 0; r < 4; r++) acc[i][j][r] = 0.0f;

    #define ISSUE_CHUNK(chunk, s)                                              \
    {                                                                          \
        uint32_t asm0 = (uint32_t)__cvta_generic_to_shared(&As[s][arow][acol]);\
        cp16(asm0,      agp + (chunk) * BK);                                   \
        cp16(asm0 + 16, agp + (chunk) * BK + 4);                               \
        uint32_t bsm0 = (uint32_t)__cvta_generic_to_shared(&Bs[s][brow][bcol]);\
        cp16(bsm0,      bgp + (size_t)(chunk) * BK * DIM);                     \
        asm volatile("cp.async.commit_group;\n" ::: "memory");                 \
    }

    ISSUE_CHUNK(0, 0)

    for (int chunk = 0; chunk < NCHUNK; chunk++) {
        asm volatile("cp.async.wait_group 0;\n" ::: "memory");
        __syncthreads();

        if (chunk + 1 < NCHUNK) ISSUE_CHUNK(chunk + 1, (chunk + 1) & 1)

        const int s = chunk & 1;
        #pragma unroll
        for (int ks = 0; ks < 2; ks++) {
            uint32_t afr[2][4], bfr[4][2];
            const int k = ks * 8 + (lane & 3);
            #pragma unroll
            for (int fm = 0; fm < 2; fm++) {
                const int m0 = warp_m + fm * 16 + (lane >> 2);
                afr[fm][0] = f2tf32(As[s][m0][k]);
                afr[fm][1] = f2tf32(As[s][m0 + 8][k]);
                afr[fm][2] = f2tf32(As[s][m0][k + 4]);
                afr[fm][3] = f2tf32(As[s][m0 + 8][k + 4]);
            }
            #pragma unroll
            for (int fn = 0; fn < 4; fn++) {
                const int nn = warp_n + fn * 8 + (lane >> 2);
                bfr[fn][0] = f2tf32(Bs[s][k][nn]);
                bfr[fn][1] = f2tf32(Bs[s][k + 4][nn]);
            }
            #pragma unroll
            for (int fm = 0; fm < 2; fm++)
                #pragma unroll
                for (int fn = 0; fn < 4; fn++)
                    mma_tf32(acc[fm][fn], afr[fm], bfr[fn]);
        }
    }
    #undef ISSUE_CHUNK

    // epilogue: bias + scatter to out rows
    #pragma unroll
    for (int fm = 0; fm < 2; fm++) {
        const int r0 = mtile * BM + warp_m + fm * 16 + (lane >> 2);
        const int r1 = r0 + 8;
        #pragma unroll
        for (int fn = 0; fn < 4; fn++) {
            const int col = n0 + warp_n + fn * 8 + 2 * (lane & 3);
            const float b0 = bias[col], b1 = bias[col + 1];
            if (r0 < cnt) {
                const int p = g_list[r0];
                float2 v = make_float2(acc[fm][fn][0] + b0, acc[fm][fn][1] + b1);
                *(float2*)&out[(size_t)p * DIM + col] = v;
            }
            if (r1 < cnt) {
                const int p = g_list[r1];
                float2 v = make_float2(acc[fm][fn][2] + b0, acc[fm][fn][3] + b1);
                *(float2*)&out[(size_t)p * DIM + col] = v;
            }
        }
    }
}

// ---------------------------------------------------------------- launch
extern "C" void kernel_launch(void* const* d_in, const int* in_sizes, int n_in,
                              void* d_out, int out_size) {
    const int*   token = (const int*)d_in[0];   // int32 or int64 (auto-detected)
    const int*   need  = (const int*)d_in[1];
    const float* emb   = (const float*)d_in[2];
    const float* W     = (const float*)d_in[3];
    const float* bias  = (const float*)d_in[4];
    float*       out   = (float*)d_out;

    k_detect_reset<<<1, 1>>>(token);
    k_compact<<<(NTOK + 255) / 256, 256>>>(token, need);
    k_copy<<<NTOK, DIM / 4>>>(token, need, (const float4*)emb, (float4*)out);
    k_gemm<<<dim3(DIM / BN, NTOK / BM), 256>>>(emb, W, bias, out);
}

// round 7
// speedup vs baseline: 1.1868x; 1.1698x over previous
#include <cuda_runtime.h>
#include <cstdint>

#define VOCAB 50000
#define DIM   768
#define NTOK  16384
#define BM    128
#define BN    64
#define KCH   32                       // K per pipeline chunk
#define NCH   (DIM / KCH)              // 24
#define NKS   (DIM / 8)                // 96 total k-steps of 8
#define A_STAGE_BYTES (BM * KCH * 4)   // 16 KB
#define B_STAGE_BYTES (BN * KCH * 4)   // 8 KB
#define STAGE_BYTES   (A_STAGE_BYTES + B_STAGE_BYTES)
#define GEMM_SMEM     (3 * STAGE_BYTES)   // 73728

__device__ int g_cnt;
__device__ int g_tok64;               // 1 if token buffer is int64
__device__ int g_list[NTOK];          // token position (output row)
__device__ int g_tok[NTOK];           // token id (embedding row)
// Fragment-packed tf32 operands (mma.sync m16n8k8 layout):
//   Ap[m16 group][kstep][lane][reg], reg = (m_hi) + 2*(k_hi)
//   Wp[n16 group][kstep][lane][reg], reg = (k_hi) + 2*(n_hi8)
__device__ uint32_t Ap[NTOK * DIM];
__device__ uint32_t Wp[DIM * DIM];

// ---------------------------------------------------------------- utilities
__device__ __forceinline__ uint32_t f2tf32(float x) {
    uint32_t r;
    asm("cvt.rna.tf32.f32 %0, %1;" : "=r"(r) : "f"(x));
    return r;
}
__device__ __forceinline__ uint32_t smem_u32(const void* p) {
    uint32_t a;
    asm("{ .reg .u64 t; cvta.to.shared.u64 t, %1; cvt.u32.u64 %0, t; }" : "=r"(a) : "l"(p));
    return a;
}
__device__ __forceinline__ void cp16(uint32_t dst, const void* src) {
    asm volatile("cp.async.cg.shared.global [%0], [%1], 16;\n" :: "r"(dst), "l"(src));
}
__device__ __forceinline__ void mma_tf32(float c[4], uint4 a, uint32_t b0, uint32_t b1) {
    asm volatile(
        "mma.sync.aligned.m16n8k8.row.col.f32.tf32.tf32.f32 "
        "{%0,%1,%2,%3}, {%4,%5,%6,%7}, {%8,%9}, {%0,%1,%2,%3};\n"
        : "+f"(c[0]), "+f"(c[1]), "+f"(c[2]), "+f"(c[3])
        : "r"(a.x), "r"(a.y), "r"(a.z), "r"(a.w), "r"(b0), "r"(b1));
}

// ---------------------------------------------------------------- small kernels
__global__ void k_detect_reset(const int* __restrict__ words) {
    // int64 tokens < 50000 -> all odd 32-bit words of first 128 elements are 0
    int v = words[threadIdx.x * 2 + 1];
    int any = __syncthreads_or(v != 0);
    if (threadIdx.x == 0) { g_tok64 = !any; g_cnt = 0; }
}

__device__ __forceinline__ int load_token(const int* __restrict__ t32, int p, int is64) {
    return is64 ? t32[2 * p] : t32[p];
}

__global__ void k_compact(const int* __restrict__ token, const int* __restrict__ need) {
    int p = blockIdx.x * blockDim.x + threadIdx.x;
    if (p < NTOK) {
        int t = load_token(token, p, g_tok64);
        if (t >= 0 && t < VOCAB && need[t]) {
            int pos = atomicAdd(&g_cnt, 1);
            g_list[pos] = p;
            g_tok[pos]  = t;
        }
    }
}

// Pack W[k][n] -> Wp fragment layout (tf32 RNA). One float4 of n per thread.
__global__ void k_wpack(const float* __restrict__ W) {
    const int gi = blockIdx.x * blockDim.x + threadIdx.x;   // DIM*DIM/4 threads
    const int k  = gi / (DIM / 4);
    const int n0 = (gi % (DIM / 4)) * 4;
    const float4 v = *(const float4*)(W + (size_t)k * DIM + n0);
    const int n16 = n0 >> 4, nh = (n0 >> 3) & 1, ln0 = n0 & 7;
    const int ks = k >> 3, lk = k & 3, kh = (k >> 2) & 1;
    const int reg = kh + 2 * nh;
    uint32_t* base = Wp + ((size_t)(n16 * NKS + ks) * 32 + ln0 * 4 + lk) * 4 + reg;
    base[0]  = f2tf32(v.x);   // lane + 1 per n -> +16 uint32
    base[16] = f2tf32(v.y);
    base[32] = f2tf32(v.z);
    base[48] = f2tf32(v.w);
}

// Fused: blocks [0,NTOK): copy non-mapped rows to out.
//        blocks [NTOK,2*NTOK): gather + RNA-tf32 + fragment-pack rows into Ap.
__global__ void k_fused(const int* __restrict__ token, const int* __restrict__ need,
                        const float* __restrict__ emb, float4* __restrict__ out) {
    const int bid = blockIdx.x;
    if (bid < NTOK) {
        const int p = bid;
        const int t = load_token(token, p, g_tok64);
        if (t < 0 || t >= VOCAB) return;
        if (need[t]) return;                         // GEMM writes these rows
        const float4* src = (const float4*)(emb + (size_t)t * DIM);
        out[(size_t)p * (DIM / 4) + threadIdx.x] = src[threadIdx.x];
    } else {
        const int r = bid - NTOK;
        const int cnt = g_cnt;
        const int cnt_pad = (cnt + BM - 1) & ~(BM - 1);
        if (r >= cnt_pad) return;
        const int m16 = r >> 4, mr = r & 15, lr = mr & 7, hi = mr >> 3;
        const int k0 = threadIdx.x * 4;              // 192 threads * 4 = 768
        const int ks = k0 >> 3, kh = (k0 >> 2) & 1;
        const int reg = hi + 2 * kh;
        uint32_t* base = Ap + ((size_t)(m16 * NKS + ks) * 32 + lr * 4) * 4 + reg;
        if (r < cnt) {
            const float4 v = *(const float4*)(emb + (size_t)g_tok[r] * DIM + k0);
            base[0]  = f2tf32(v.x);                  // lane + 1 per k -> +4 uint32
            base[4]  = f2tf32(v.y);
            base[8]  = f2tf32(v.z);
            base[12] = f2tf32(v.w);
        } else {
            base[0] = 0; base[4] = 0; base[8] = 0; base[12] = 0;
        }
    }
}

// ---------------------------------------------------------------- GEMM
// out[g_list[r]] = emb_row(r) @ W + bias over r < g_cnt, operands pre-packed.
// CTA 128x64, 8 warps 4Mx2N, warp tile 32x32 (acc 32 regs), 3-stage cp.async.
__global__ __launch_bounds__(256, 2) void k_gemm(const float* __restrict__ bias,
                                                 float* __restrict__ out) {
    const int cnt = g_cnt;
    const int mtile = blockIdx.y;
    if (mtile * BM >= cnt) return;
    const int n16_0 = blockIdx.x * (BN / 16);
    const int n0 = blockIdx.x * BN;

    extern __shared__ uint32_t smem[];   // 3 stages x (A 16KB | B 8KB)

    const int tid  = threadIdx.x;
    const int lane = tid & 31;
    const int wid  = tid >> 5;
    const int wm   = wid >> 1;           // 0..3 (M)
    const int wn   = wid & 1;            // 0..1 (N)

    float acc[2][4][4];
    #pragma unroll
    for (int i = 0; i < 2; i++)
        #pragma unroll
        for (int j = 0; j < 4; j++)
            #pragma unroll
            for (int r = 0; r < 4; r++) acc[i][j][r] = 0.0f;

    #define ISSUE(c, s)                                                          \
    {                                                                            \
        const uint32_t dstA = smem_u32(smem) + (s) * STAGE_BYTES;                \
        const uint32_t dstB = dstA + A_STAGE_BYTES;                              \
        _Pragma("unroll")                                                        \
        for (int j = 0; j < 4; j++) {                                            \
            const int idx = tid + j * 256;       /* 0..1023: A = 8 x 2KB */      \
            const int piece = idx >> 7, off = idx & 127;                         \
            const uint32_t* src =                                                \
                Ap + (size_t)((mtile * 8 + piece) * NKS + (c) * 4) * 128 + off * 4; \
            cp16(dstA + piece * 2048 + off * 16, src);                           \
        }                                                                        \
        _Pragma("unroll")                                                        \
        for (int j = 0; j < 2; j++) {                                            \
            const int idx = tid + j * 256;       /* 0..511: B = 4 x 2KB */       \
            const int piece = idx >> 7, off = idx & 127;                         \
            const uint32_t* src =                                                \
                Wp + (size_t)((n16_0 + piece) * NKS + (c) * 4) * 128 + off * 4;  \
            cp16(dstB + piece * 2048 + off * 16, src);                           \
        }                                                                        \
        asm volatile("cp.async.commit_group;\n" ::: "memory");                   \
    }

    ISSUE(0, 0)
    ISSUE(1, 1)

    for (int c = 0; c < NCH; c++) {
        if (c + 2 < NCH) asm volatile("cp.async.wait_group 1;\n" ::: "memory");
        else             asm volatile("cp.async.wait_group 0;\n" ::: "memory");
        __syncthreads();
        if (c + 2 < NCH) ISSUE(c + 2, (c + 2) % 3)

        const uint32_t* aS = smem + (c % 3) * (STAGE_BYTES / 4);
        const uint32_t* bS = aS + (A_STAGE_BYTES / 4);
        #pragma unroll
        for (int ks = 0; ks < 4; ks++) {
            const uint4 a0 = *(const uint4*)(aS + (((wm * 2 + 0) * 4 + ks) * 32 + lane) * 4);
            const uint4 a1 = *(const uint4*)(aS + (((wm * 2 + 1) * 4 + ks) * 32 + lane) * 4);
            const uint4 b0 = *(const uint4*)(bS + (((wn * 2 + 0) * 4 + ks) * 32 + lane) * 4);
            const uint4 b1 = *(const uint4*)(bS + (((wn * 2 + 1) * 4 + ks) * 32 + lane) * 4);
            mma_tf32(acc[0][0], a0, b0.x, b0.y);
            mma_tf32(acc[0][1], a0, b0.z, b0.w);
            mma_tf32(acc[0][2], a0, b1.x, b1.y);
            mma_tf32(acc[0][3], a0, b1.z, b1.w);
            mma_tf32(acc[1][0], a1, b0.x, b0.y);
            mma_tf32(acc[1][1], a1, b0.z, b0.w);
            mma_tf32(acc[1][2], a1, b1.x, b1.y);
            mma_tf32(acc[1][3], a1, b1.z, b1.w);
        }
    }
    #undef ISSUE

    // epilogue: bias + scatter to out rows
    #pragma unroll
    for (int fm = 0; fm < 2; fm++) {
        const int r0 = mtile * BM + (wm * 2 + fm) * 16 + (lane >> 2);
        const int r1 = r0 + 8;
        #pragma unroll
        for (int fn = 0; fn < 4; fn++) {
            const int g = fn >> 1, sub = fn & 1;
            const int col = n0 + (wn * 2 + g) * 16 + sub * 8 + (lane & 3) * 2;
            const float b0 = bias[col], b1 = bias[col + 1];
            if (r0 < cnt) {
                const int p = g_list[r0];
                float2 v = make_float2(acc[fm][fn][0] + b0, acc[fm][fn][1] + b1);
                *(float2*)&out[(size_t)p * DIM + col] = v;
            }
            if (r1 < cnt) {
                const int p = g_list[r1];
                float2 v = make_float2(acc[fm][fn][2] + b0, acc[fm][fn][3] + b1);
                *(float2*)&out[(size_t)p * DIM + col] = v;
            }
        }
    }
}

// ---------------------------------------------------------------- launch
extern "C" void kernel_launch(void* const* d_in, const int* in_sizes, int n_in,
                              void* d_out, int out_size) {
    const int*   token = (const int*)d_in[0];   // int32 or int64 (auto-detected)
    const int*   need  = (const int*)d_in[1];
    const float* emb   = (const float*)d_in[2];
    const float* W     = (const float*)d_in[3];
    const float* bias  = (const float*)d_in[4];
    float*       out   = (float*)d_out;

    cudaFuncSetAttribute(k_gemm, cudaFuncAttributeMaxDynamicSharedMemorySize, GEMM_SMEM);

    k_detect_reset<<<1, 128>>>(token);
    k_compact<<<(NTOK + 255) / 256, 256>>>(token, need);
    k_wpack<<<(DIM * DIM / 4) / 256, 256>>>(W);
    k_fused<<<2 * NTOK, DIM / 4>>>(token, need, emb, (float4*)out);
    k_gemm<<<dim3(DIM / BN, NTOK / BM), 256, GEMM_SMEM>>>(bias, out);
}

// round 8
// speedup vs baseline: 1.8723x; 1.5776x over previous
#include <cuda_runtime.h>
#include <cuda_fp16.h>
#include <cstdint>

#define VOCAB 50000
#define DIM   768
#define NTOK  16384
#define BM    128
#define BN    64
#define KCH   64                       // K per pipeline chunk (4 k16-steps)
#define NCH   (DIM / KCH)              // 12
#define NKS   (DIM / 16)               // 48 k16-steps per row
#define NM16  (NTOK / 16)              // 1024 fragment row-groups
#define A_STAGE_BYTES (BM * KCH * 2)   // 16 KB (fp16)
#define B_STAGE_BYTES (BN * KCH * 2)   // 8 KB
#define STAGE_BYTES   (A_STAGE_BYTES + B_STAGE_BYTES)
#define GEMM_SMEM     (3 * STAGE_BYTES)   // 72 KB

__device__ int g_cnt;
__device__ int g_tok64;               // 1 if token buffer is int64
__device__ int g_list[NTOK];          // token position (output row)
__device__ int g_tok[NTOK];           // token id (embedding row)
// Fragment-packed fp16 operands for mma.sync m16n8k16 (row.col):
//   Ap[(m16*NKS + ks)*32 + lane] = uint4 {a0,a1,a2,a3}
//   Wp[(n16*NKS + ks)*32 + lane] = uint4 {b0@n,b1@n,b0@n+8,b1@n+8}
__device__ uint4 Ap[NM16 * NKS * 32];
__device__ uint4 Wp[(DIM / 16) * NKS * 32];

// ---------------------------------------------------------------- utilities
__device__ __forceinline__ uint32_t f2h2(float x, float y) {
    __half2 h = __floats2half2_rn(x, y);
    return *(uint32_t*)&h;
}
__device__ __forceinline__ uint32_t smem_u32(const void* p) {
    uint32_t a;
    asm("{ .reg .u64 t; cvta.to.shared.u64 t, %1; cvt.u32.u64 %0, t; }" : "=r"(a) : "l"(p));
    return a;
}
__device__ __forceinline__ void cp16(uint32_t dst, const void* src) {
    asm volatile("cp.async.cg.shared.global [%0], [%1], 16;\n" :: "r"(dst), "l"(src));
}
__device__ __forceinline__ void mma_f16(float c[4], uint4 a, uint32_t b0, uint32_t b1) {
    asm volatile(
        "mma.sync.aligned.m16n8k16.row.col.f32.f16.f16.f32 "
        "{%0,%1,%2,%3}, {%4,%5,%6,%7}, {%8,%9}, {%0,%1,%2,%3};\n"
        : "+f"(c[0]), "+f"(c[1]), "+f"(c[2]), "+f"(c[3])
        : "r"(a.x), "r"(a.y), "r"(a.z), "r"(a.w), "r"(b0), "r"(b1));
}

// ---------------------------------------------------------------- small kernels
__global__ void k_detect_reset(const int* __restrict__ words) {
    // int64 tokens < 50000 -> all odd 32-bit words of first 128 elements are 0
    int v = words[threadIdx.x * 2 + 1];
    int any = __syncthreads_or(v != 0);
    if (threadIdx.x == 0) { g_tok64 = !any; g_cnt = 0; }
}

__device__ __forceinline__ int load_token(const int* __restrict__ t32, int p, int is64) {
    return is64 ? t32[2 * p] : t32[p];
}

__global__ void k_compact(const int* __restrict__ token, const int* __restrict__ need) {
    int p = blockIdx.x * blockDim.x + threadIdx.x;
    if (p < NTOK) {
        int t = load_token(token, p, g_tok64);
        if (t >= 0 && t < VOCAB && need[t]) {
            int pos = atomicAdd(&g_cnt, 1);
            g_list[pos] = p;
            g_tok[pos]  = t;
        }
    }
}

// Pack W[k][n] -> B fragments. One thread per (n16, ks, lane) -> one uint4.
__global__ void k_wpack(const float* __restrict__ W) {
    const int gi = blockIdx.x * blockDim.x + threadIdx.x;   // 48*48*32 threads
    const int lane = gi & 31;
    const int ks   = (gi >> 5) % NKS;
    const int n16  = gi / (NKS * 32);
    const int na = n16 * 16 + (lane >> 2);
    const int nb = na + 8;
    const int k0 = ks * 16 + (lane & 3) * 2;
    uint4 o;
    o.x = f2h2(W[(size_t)k0 * DIM + na],       W[(size_t)(k0 + 1) * DIM + na]);
    o.y = f2h2(W[(size_t)(k0 + 8) * DIM + na], W[(size_t)(k0 + 9) * DIM + na]);
    o.z = f2h2(W[(size_t)k0 * DIM + nb],       W[(size_t)(k0 + 1) * DIM + nb]);
    o.w = f2h2(W[(size_t)(k0 + 8) * DIM + nb], W[(size_t)(k0 + 9) * DIM + nb]);
    Wp[(size_t)(n16 * NKS + ks) * 32 + lane] = o;
}

// Fused: blocks [0,NTOK): copy non-mapped rows to out (128 threads).
//        blocks [NTOK,NTOK+NM16): pack one 16-row fragment group into Ap,
//        coalesced uint4 stores (512B per warp-write).
__global__ void k_fused(const int* __restrict__ token, const int* __restrict__ need,
                        const float* __restrict__ emb, float4* __restrict__ out) {
    const int bid = blockIdx.x;
    if (bid < NTOK) {
        const int p = bid;
        const int t = load_token(token, p, g_tok64);
        if (t < 0 || t >= VOCAB) return;
        if (need[t]) return;                         // GEMM writes these rows
        const float4* src = (const float4*)(emb + (size_t)t * DIM);
        float4* dst = out + (size_t)p * (DIM / 4);
        const int i = threadIdx.x;                   // 128 threads, 192 float4
        dst[i] = src[i];
        if (i < 64) dst[i + 128] = src[i + 128];
    } else {
        const int m16 = bid - NTOK;
        const int cnt = g_cnt;
        const int cnt_pad = (cnt + BM - 1) & ~(BM - 1);
        if (m16 * 16 >= cnt_pad) return;
        const int wid = threadIdx.x >> 5, lane = threadIdx.x & 31;
        const int lr = lane >> 2, lk = lane & 3;
        const int r0 = m16 * 16 + lr, r1 = r0 + 8;
        const bool v0 = r0 < cnt, v1 = r1 < cnt;
        const float* e0 = emb + (size_t)(v0 ? g_tok[r0] : 0) * DIM;
        const float* e1 = emb + (size_t)(v1 ? g_tok[r1] : 0) * DIM;
        const float2 z2 = make_float2(0.f, 0.f);
        #pragma unroll
        for (int j = 0; j < NKS / 4; j++) {          // 4 warps x 12 ksteps
            const int ks = wid * (NKS / 4) + j;
            const int k0 = ks * 16 + lk * 2;
            const float2 p0 = v0 ? *(const float2*)(e0 + k0)     : z2;
            const float2 p2 = v0 ? *(const float2*)(e0 + k0 + 8) : z2;
            const float2 p1 = v1 ? *(const float2*)(e1 + k0)     : z2;
            const float2 p3 = v1 ? *(const float2*)(e1 + k0 + 8) : z2;
            uint4 o;
            o.x = f2h2(p0.x, p0.y);
            o.y = f2h2(p1.x, p1.y);
            o.z = f2h2(p2.x, p2.y);
            o.w = f2h2(p3.x, p3.y);
            Ap[(size_t)(m16 * NKS + ks) * 32 + lane] = o;
        }
    }
}

// ---------------------------------------------------------------- GEMM
// out[g_list[r]] = emb_row(r) @ W + bias, fp16 fragment-packed operands.
// CTA 128x64, 8 warps 4Mx2N, warp tile 32x32, 3-stage cp.async, NCH=12.
__global__ __launch_bounds__(256, 2) void k_gemm(const float* __restrict__ bias,
                                                 float* __restrict__ out) {
    const int cnt = g_cnt;
    const int mtile = blockIdx.y;
    if (mtile * BM >= cnt) return;
    const int n16_0 = blockIdx.x * (BN / 16);
    const int n0 = blockIdx.x * BN;

    extern __shared__ uint32_t smem[];   // 3 stages x (A 16KB | B 8KB)

    const int tid  = threadIdx.x;
    const int lane = tid & 31;
    const int wid  = tid >> 5;
    const int wm   = wid >> 1;           // 0..3 (M)
    const int wn   = wid & 1;            // 0..1 (N)

    float acc[2][4][4];
    #pragma unroll
    for (int i = 0; i < 2; i++)
        #pragma unroll
        for (int j = 0; j < 4; j++)
            #pragma unroll
            for (int r = 0; r < 4; r++) acc[i][j][r] = 0.0f;

    // Stage layout: A pieces (8 x 2KB), then B pieces (4 x 2KB); a piece is
    // one (m16|n16 group, 4 ksteps) = contiguous 2KB in Ap/Wp.
    #define ISSUE(c, s)                                                          \
    {                                                                            \
        const uint32_t dstA = smem_u32(smem) + (s) * STAGE_BYTES;                \
        const uint32_t dstB = dstA + A_STAGE_BYTES;                              \
        _Pragma("unroll")                                                        \
        for (int j = 0; j < 4; j++) {                                            \
            const int idx = tid + j * 256;       /* 0..1023 */                   \
            const int piece = idx >> 7, off = idx & 127;                         \
            const uint4* src =                                                   \
                Ap + (size_t)((mtile * 8 + piece) * NKS + (c) * 4) * 32 + off;   \
            cp16(dstA + piece * 2048 + off * 16, src);                           \
        }                                                                        \
        _Pragma("unroll")                                                        \
        for (int j = 0; j < 2; j++) {                                            \
            const int idx = tid + j * 256;       /* 0..511 */                    \
            const int piece = idx >> 7, off = idx & 127;                         \
            const uint4* src =                                                   \
                Wp + (size_t)((n16_0 + piece) * NKS + (c) * 4) * 32 + off;       \
            cp16(dstB + piece * 2048 + off * 16, src);                           \
        }                                                                        \
        asm volatile("cp.async.commit_group;\n" ::: "memory");                   \
    }

    ISSUE(0, 0)
    ISSUE(1, 1)

    for (int c = 0; c < NCH; c++) {
        if (c + 2 < NCH) asm volatile("cp.async.wait_group 1;\n" ::: "memory");
        else             asm volatile("cp.async.wait_group 0;\n" ::: "memory");
        __syncthreads();
        if (c + 2 < NCH) ISSUE(c + 2, (c + 2) % 3)

        const uint32_t* aS = smem + (c % 3) * (STAGE_BYTES / 4);
        const uint32_t* bS = aS + (A_STAGE_BYTES / 4);
        #pragma unroll
        for (int ks = 0; ks < 4; ks++) {
            const uint4 a0 = *(const uint4*)(aS + ((wm * 2 + 0) * 512 + ks * 128 + lane * 4));
            const uint4 a1 = *(const uint4*)(aS + ((wm * 2 + 1) * 512 + ks * 128 + lane * 4));
            const uint4 b0 = *(const uint4*)(bS + ((wn * 2 + 0) * 512 + ks * 128 + lane * 4));
            const uint4 b1 = *(const uint4*)(bS + ((wn * 2 + 1) * 512 + ks * 128 + lane * 4));
            mma_f16(acc[0][0], a0, b0.x, b0.y);
            mma_f16(acc[0][1], a0, b0.z, b0.w);
            mma_f16(acc[0][2], a0, b1.x, b1.y);
            mma_f16(acc[0][3], a0, b1.z, b1.w);
            mma_f16(acc[1][0], a1, b0.x, b0.y);
            mma_f16(acc[1][1], a1, b0.z, b0.w);
            mma_f16(acc[1][2], a1, b1.x, b1.y);
            mma_f16(acc[1][3], a1, b1.z, b1.w);
        }
    }
    #undef ISSUE

    // epilogue: bias + scatter to out rows
    #pragma unroll
    for (int fm = 0; fm < 2; fm++) {
        const int r0 = mtile * BM + (wm * 2 + fm) * 16 + (lane >> 2);
        const int r1 = r0 + 8;
        #pragma unroll
        for (int fn = 0; fn < 4; fn++) {
            const int g = fn >> 1, sub = fn & 1;
            const int col = n0 + (wn * 2 + g) * 16 + sub * 8 + (lane & 3) * 2;
            const float b0 = bias[col], b1 = bias[col + 1];
            if (r0 < cnt) {
                const int p = g_list[r0];
                float2 v = make_float2(acc[fm][fn][0] + b0, acc[fm][fn][1] + b1);
                *(float2*)&out[(size_t)p * DIM + col] = v;
            }
            if (r1 < cnt) {
                const int p = g_list[r1];
                float2 v = make_float2(acc[fm][fn][2] + b0, acc[fm][fn][3] + b1);
                *(float2*)&out[(size_t)p * DIM + col] = v;
            }
        }
    }
}

// ---------------------------------------------------------------- launch
extern "C" void kernel_launch(void* const* d_in, const int* in_sizes, int n_in,
                              void* d_out, int out_size) {
    const int*   token = (const int*)d_in[0];   // int32 or int64 (auto-detected)
    const int*   need  = (const int*)d_in[1];
    const float* emb   = (const float*)d_in[2];
    const float* W     = (const float*)d_in[3];
    const float* bias  = (const float*)d_in[4];
    float*       out   = (float*)d_out;

    cudaFuncSetAttribute(k_gemm, cudaFuncAttributeMaxDynamicSharedMemorySize, GEMM_SMEM);

    k_detect_reset<<<1, 128>>>(token);
    k_compact<<<(NTOK + 255) / 256, 256>>>(token, need);
    k_wpack<<<(48 * NKS * 32) / 256, 256>>>(W);
    k_fused<<<NTOK + NM16, 128>>>(token, need, emb, (float4*)out);
    k_gemm<<<dim3(DIM / BN, NTOK / BM), 256, GEMM_SMEM>>>(bias, out);
}

// round 9
// speedup vs baseline: 2.0748x; 1.1082x over previous
#include <cuda_runtime.h>
#include <cuda_fp16.h>
#include <cstdint>

#define VOCAB 50000
#define DIM   768
#define NTOK  16384
#define BM    128
#define BN    64
#define KCH   64                       // K per pipeline chunk (4 k16-steps)
#define NCH   (DIM / KCH)              // 12
#define NKS   (DIM / 16)               // 48 k16-steps per row
#define NM16  (NTOK / 16)              // 1024 fragment row-groups
#define A_STAGE_BYTES (BM * KCH * 2)   // 16 KB (fp16)
#define B_STAGE_BYTES (BN * KCH * 2)   // 8 KB
#define STAGE_BYTES   (A_STAGE_BYTES + B_STAGE_BYTES)
#define GEMM_SMEM     (3 * STAGE_BYTES)   // 72 KB

// mega-kernel block ranges
#define NB_COPY  (NTOK / 8)            // 2048: warp-per-row copy
#define NB_PACK  (NM16 / 2)            // 512:  2 m16-groups per block
#define NB_WPACK ((48 * NKS * 32) / 256)  // 288
#define NB_TOTAL (NB_COPY + NB_PACK + NB_WPACK)

__device__ int g_cnt;
__device__ int g_tok64;               // 1 if token buffer is int64
__device__ int g_list[NTOK];          // token position (output row)
__device__ int g_tok[NTOK];           // token id (embedding row)
// Fragment-packed fp16 operands for mma.sync m16n8k16 (row.col):
//   Ap[(m16*NKS + ks)*32 + lane] = uint4 {a0,a1,a2,a3}
//   Wp[(n16*NKS + ks)*32 + lane] = uint4 {b0@n,b1@n,b0@n+8,b1@n+8}
__device__ uint4 Ap[NM16 * NKS * 32];
__device__ uint4 Wp[(DIM / 16) * NKS * 32];

// ---------------------------------------------------------------- utilities
__device__ __forceinline__ uint32_t f2h2(float x, float y) {
    __half2 h = __floats2half2_rn(x, y);
    return *(uint32_t*)&h;
}
__device__ __forceinline__ uint32_t smem_u32(const void* p) {
    uint32_t a;
    asm("{ .reg .u64 t; cvta.to.shared.u64 t, %1; cvt.u32.u64 %0, t; }" : "=r"(a) : "l"(p));
    return a;
}
__device__ __forceinline__ void cp16(uint32_t dst, const void* src) {
    asm volatile("cp.async.cg.shared.global [%0], [%1], 16;\n" :: "r"(dst), "l"(src));
}
__device__ __forceinline__ void mma_f16(float c[4], uint4 a, uint32_t b0, uint32_t b1) {
    asm volatile(
        "mma.sync.aligned.m16n8k16.row.col.f32.f16.f16.f32 "
        "{%0,%1,%2,%3}, {%4,%5,%6,%7}, {%8,%9}, {%0,%1,%2,%3};\n"
        : "+f"(c[0]), "+f"(c[1]), "+f"(c[2]), "+f"(c[3])
        : "r"(a.x), "r"(a.y), "r"(a.z), "r"(a.w), "r"(b0), "r"(b1));
}

// ---------------------------------------------------------------- small kernels
__global__ void k_detect_reset(const int* __restrict__ words) {
    // int64 tokens < 50000 -> all odd 32-bit words of first 128 elements are 0
    int v = words[threadIdx.x * 2 + 1];
    int any = __syncthreads_or(v != 0);
    if (threadIdx.x == 0) { g_tok64 = !any; g_cnt = 0; }
}

__device__ __forceinline__ int load_token(const int* __restrict__ t32, int p, int is64) {
    return is64 ? t32[2 * p] : t32[p];
}

__global__ void k_compact(const int* __restrict__ token, const int* __restrict__ need) {
    int p = blockIdx.x * blockDim.x + threadIdx.x;
    if (p < NTOK) {
        int t = load_token(token, p, g_tok64);
        if (t >= 0 && t < VOCAB && need[t]) {
            int pos = atomicAdd(&g_cnt, 1);
            g_list[pos] = p;
            g_tok[pos]  = t;
        }
    }
}

// Mega kernel: [0,NB_COPY): warp-per-row copy of non-mapped rows (6 indep
// float4 loads/lane); [NB_COPY,+NB_PACK): A fragment pack, 2 m16-groups per
// block, j-unrolled x2 for MLP; [+NB_WPACK): W fragment pack.
__global__ void k_mega(const int* __restrict__ token, const int* __restrict__ need,
                       const float* __restrict__ emb, const float* __restrict__ W,
                       float4* __restrict__ out) {
    const int bid  = blockIdx.x;
    const int tid  = threadIdx.x;
    const int wid  = tid >> 5;
    const int lane = tid & 31;

    if (bid < NB_COPY) {
        // ---- copy branch: one warp per token row
        const int p = bid * 8 + wid;
        const int t = load_token(token, p, g_tok64);
        if (t < 0 || t >= VOCAB) return;
        if (need[t]) return;                         // GEMM writes these rows
        const float4* src = (const float4*)(emb + (size_t)t * DIM);
        float4* dst = out + (size_t)p * (DIM / 4);
        float4 v0 = src[lane];
        float4 v1 = src[lane + 32];
        float4 v2 = src[lane + 64];
        float4 v3 = src[lane + 96];
        float4 v4 = src[lane + 128];
        float4 v5 = src[lane + 160];
        dst[lane]       = v0;
        dst[lane + 32]  = v1;
        dst[lane + 64]  = v2;
        dst[lane + 96]  = v3;
        dst[lane + 128] = v4;
        dst[lane + 160] = v5;
    } else if (bid < NB_COPY + NB_PACK) {
        // ---- A pack branch: 8 warps = 2 m16-groups x 4 warps
        const int cnt = g_cnt;
        const int cnt_pad = (cnt + BM - 1) & ~(BM - 1);
        const int m16 = (bid - NB_COPY) * 2 + (wid >> 2);
        if (m16 * 16 >= cnt_pad) return;
        const int wg = wid & 3;                      // warp within group
        const int lr = lane >> 2, lk = lane & 3;
        const int r0 = m16 * 16 + lr, r1 = r0 + 8;
        const bool v0 = r0 < cnt, v1 = r1 < cnt;
        const float* e0 = emb + (size_t)(v0 ? g_tok[r0] : 0) * DIM;
        const float* e1 = emb + (size_t)(v1 ? g_tok[r1] : 0) * DIM;
        const float2 z2 = make_float2(0.f, 0.f);
        #pragma unroll
        for (int j = 0; j < NKS / 4; j += 2) {       // 12 ksteps, 2 at a time
            const int ksA = wg * (NKS / 4) + j;
            const int kA = ksA * 16 + lk * 2;
            const int kB = kA + 16;
            // 8 independent gathers in flight
            const float2 a0 = v0 ? *(const float2*)(e0 + kA)     : z2;
            const float2 a2 = v0 ? *(const float2*)(e0 + kA + 8) : z2;
            const float2 a1 = v1 ? *(const float2*)(e1 + kA)     : z2;
            const float2 a3 = v1 ? *(const float2*)(e1 + kA + 8) : z2;
            const float2 b0 = v0 ? *(const float2*)(e0 + kB)     : z2;
            const float2 b2 = v0 ? *(const float2*)(e0 + kB + 8) : z2;
            const float2 b1 = v1 ? *(const float2*)(e1 + kB)     : z2;
            const float2 b3 = v1 ? *(const float2*)(e1 + kB + 8) : z2;
            uint4 oA, oB;
            oA.x = f2h2(a0.x, a0.y); oA.y = f2h2(a1.x, a1.y);
            oA.z = f2h2(a2.x, a2.y); oA.w = f2h2(a3.x, a3.y);
            oB.x = f2h2(b0.x, b0.y); oB.y = f2h2(b1.x, b1.y);
            oB.z = f2h2(b2.x, b2.y); oB.w = f2h2(b3.x, b3.y);
            Ap[(size_t)(m16 * NKS + ksA) * 32 + lane]     = oA;
            Ap[(size_t)(m16 * NKS + ksA + 1) * 32 + lane] = oB;
        }
    } else {
        // ---- W pack branch
        const int gi = (bid - NB_COPY - NB_PACK) * 256 + tid;   // 48*48*32
        const int lane_w = gi & 31;
        const int ks   = (gi >> 5) % NKS;
        const int n16  = gi / (NKS * 32);
        const int na = n16 * 16 + (lane_w >> 2);
        const int nb = na + 8;
        const int k0 = ks * 16 + (lane_w & 3) * 2;
        uint4 o;
        o.x = f2h2(W[(size_t)k0 * DIM + na],       W[(size_t)(k0 + 1) * DIM + na]);
        o.y = f2h2(W[(size_t)(k0 + 8) * DIM + na], W[(size_t)(k0 + 9) * DIM + na]);
        o.z = f2h2(W[(size_t)k0 * DIM + nb],       W[(size_t)(k0 + 1) * DIM + nb]);
        o.w = f2h2(W[(size_t)(k0 + 8) * DIM + nb], W[(size_t)(k0 + 9) * DIM + nb]);
        Wp[(size_t)(n16 * NKS + ks) * 32 + lane_w] = o;
    }
}

// ---------------------------------------------------------------- GEMM
// out[g_list[r]] = emb_row(r) @ W + bias, fp16 fragment-packed operands.
// CTA 128x64, 8 warps 4Mx2N, warp tile 32x32, 3-stage cp.async, NCH=12.
__global__ __launch_bounds__(256, 2) void k_gemm(const float* __restrict__ bias,
                                                 float* __restrict__ out) {
    const int cnt = g_cnt;
    const int mtile = blockIdx.y;
    if (mtile * BM >= cnt) return;
    const int n16_0 = blockIdx.x * (BN / 16);
    const int n0 = blockIdx.x * BN;

    extern __shared__ uint32_t smem[];   // 3 stages x (A 16KB | B 8KB)

    const int tid  = threadIdx.x;
    const int lane = tid & 31;
    const int wid  = tid >> 5;
    const int wm   = wid >> 1;           // 0..3 (M)
    const int wn   = wid & 1;            // 0..1 (N)

    float acc[2][4][4];
    #pragma unroll
    for (int i = 0; i < 2; i++)
        #pragma unroll
        for (int j = 0; j < 4; j++)
            #pragma unroll
            for (int r = 0; r < 4; r++) acc[i][j][r] = 0.0f;

    #define ISSUE(c, s)                                                          \
    {                                                                            \
        const uint32_t dstA = smem_u32(smem) + (s) * STAGE_BYTES;                \
        const uint32_t dstB = dstA + A_STAGE_BYTES;                              \
        _Pragma("unroll")                                                        \
        for (int j = 0; j < 4; j++) {                                            \
            const int idx = tid + j * 256;       /* 0..1023 */                   \
            const int piece = idx >> 7, off = idx & 127;                         \
            const uint4* src =                                                   \
                Ap + (size_t)((mtile * 8 + piece) * NKS + (c) * 4) * 32 + off;   \
            cp16(dstA + piece * 2048 + off * 16, src);                           \
        }                                                                        \
        _Pragma("unroll")                                                        \
        for (int j = 0; j < 2; j++) {                                            \
            const int idx = tid + j * 256;       /* 0..511 */                    \
            const int piece = idx >> 7, off = idx & 127;                         \
            const uint4* src =                                                   \
                Wp + (size_t)((n16_0 + piece) * NKS + (c) * 4) * 32 + off;       \
            cp16(dstB + piece * 2048 + off * 16, src);                           \
        }                                                                        \
        asm volatile("cp.async.commit_group;\n" ::: "memory");                   \
    }

    ISSUE(0, 0)
    ISSUE(1, 1)

    for (int c = 0; c < NCH; c++) {
        if (c + 2 < NCH) asm volatile("cp.async.wait_group 1;\n" ::: "memory");
        else             asm volatile("cp.async.wait_group 0;\n" ::: "memory");
        __syncthreads();
        if (c + 2 < NCH) ISSUE(c + 2, (c + 2) % 3)

        const uint32_t* aS = smem + (c % 3) * (STAGE_BYTES / 4);
        const uint32_t* bS = aS + (A_STAGE_BYTES / 4);
        #pragma unroll
        for (int ks = 0; ks < 4; ks++) {
            const uint4 a0 = *(const uint4*)(aS + ((wm * 2 + 0) * 512 + ks * 128 + lane * 4));
            const uint4 a1 = *(const uint4*)(aS + ((wm * 2 + 1) * 512 + ks * 128 + lane * 4));
            const uint4 b0 = *(const uint4*)(bS + ((wn * 2 + 0) * 512 + ks * 128 + lane * 4));
            const uint4 b1 = *(const uint4*)(bS + ((wn * 2 + 1) * 512 + ks * 128 + lane * 4));
            mma_f16(acc[0][0], a0, b0.x, b0.y);
            mma_f16(acc[0][1], a0, b0.z, b0.w);
            mma_f16(acc[0][2], a0, b1.x, b1.y);
            mma_f16(acc[0][3], a0, b1.z, b1.w);
            mma_f16(acc[1][0], a1, b0.x, b0.y);
            mma_f16(acc[1][1], a1, b0.z, b0.w);
            mma_f16(acc[1][2], a1, b1.x, b1.y);
            mma_f16(acc[1][3], a1, b1.z, b1.w);
        }
    }
    #undef ISSUE

    // epilogue: bias + scatter to out rows
    #pragma unroll
    for (int fm = 0; fm < 2; fm++) {
        const int r0 = mtile * BM + (wm * 2 + fm) * 16 + (lane >> 2);
        const int r1 = r0 + 8;
        #pragma unroll
        for (int fn = 0; fn < 4; fn++) {
            const int g = fn >> 1, sub = fn & 1;
            const int col = n0 + (wn * 2 + g) * 16 + sub * 8 + (lane & 3) * 2;
            const float b0 = bias[col], b1 = bias[col + 1];
            if (r0 < cnt) {
                const int p = g_list[r0];
                float2 v = make_float2(acc[fm][fn][0] + b0, acc[fm][fn][1] + b1);
                *(float2*)&out[(size_t)p * DIM + col] = v;
            }
            if (r1 < cnt) {
                const int p = g_list[r1];
                float2 v = make_float2(acc[fm][fn][2] + b0, acc[fm][fn][3] + b1);
                *(float2*)&out[(size_t)p * DIM + col] = v;
            }
        }
    }
}

// ---------------------------------------------------------------- launch
extern "C" void kernel_launch(void* const* d_in, const int* in_sizes, int n_in,
                              void* d_out, int out_size) {
    const int*   token = (const int*)d_in[0];   // int32 or int64 (auto-detected)
    const int*   need  = (const int*)d_in[1];
    const float* emb   = (const float*)d_in[2];
    const float* W     = (const float*)d_in[3];
    const float* bias  = (const float*)d_in[4];
    float*       out   = (float*)d_out;

    cudaFuncSetAttribute(k_gemm, cudaFuncAttributeMaxDynamicSharedMemorySize, GEMM_SMEM);

    k_detect_reset<<<1, 128>>>(token);
    k_compact<<<(NTOK + 255) / 256, 256>>>(token, need);
    k_mega<<<NB_TOTAL, 256>>>(token, need, emb, W, (float4*)out);
    k_gemm<<<dim3(DIM / BN, NTOK / BM), 256, GEMM_SMEM>>>(bias, out);
}

// round 10
// speedup vs baseline: 2.0843x; 1.0046x over previous
#include <cuda_runtime.h>
#include <cuda_fp16.h>
#include <cstdint>

#define VOCAB 50000
#define DIM   768
#define NTOK  16384
#define BM    128
#define BN    64
#define KCH   128                      // K per pipeline chunk (8 k16-steps)
#define NCH   (DIM / KCH)              // 6
#define NKS   (DIM / 16)               // 48 k16-steps per row
#define NM16  (NTOK / 16)              // 1024 fragment row-groups
#define NTILE_N (DIM / BN)             // 12
#define A_STAGE_BYTES (BM * KCH * 2)   // 32 KB (fp16)
#define B_STAGE_BYTES (BN * KCH * 2)   // 16 KB
#define STAGE_BYTES   (A_STAGE_BYTES + B_STAGE_BYTES)
#define GEMM_SMEM     (2 * STAGE_BYTES)   // 96 KB
#define GEMM_GRID     296              // persistent: ~2 CTAs/SM

// mega-kernel block ranges
#define NB_COPY  (NTOK / 8)            // 2048: warp-per-row copy
#define NB_PACK  (NM16 / 2)            // 512:  2 m16-groups per block
#define NB_WPACK ((48 * NKS * 32) / 256)  // 288
#define NB_TOTAL (NB_COPY + NB_PACK + NB_WPACK)

__device__ int g_cnt;
__device__ int g_tok64;               // 1 if token buffer is int64
__device__ int g_list[NTOK];          // token position (output row)
__device__ int g_tok[NTOK];           // token id (embedding row)
// Fragment-packed fp16 operands for mma.sync m16n8k16 (row.col):
//   Ap[(m16*NKS + ks)*32 + lane] = uint4 {a0,a1,a2,a3}
//   Wp[(n16*NKS + ks)*32 + lane] = uint4 {b0@n,b1@n,b0@n+8,b1@n+8}
__device__ uint4 Ap[NM16 * NKS * 32];
__device__ uint4 Wp[(DIM / 16) * NKS * 32];

// ---------------------------------------------------------------- utilities
__device__ __forceinline__ uint32_t f2h2(float x, float y) {
    __half2 h = __floats2half2_rn(x, y);
    return *(uint32_t*)&h;
}
__device__ __forceinline__ uint32_t smem_u32(const void* p) {
    uint32_t a;
    asm("{ .reg .u64 t; cvta.to.shared.u64 t, %1; cvt.u32.u64 %0, t; }" : "=r"(a) : "l"(p));
    return a;
}
__device__ __forceinline__ void cp16(uint32_t dst, const void* src) {
    asm volatile("cp.async.cg.shared.global [%0], [%1], 16;\n" :: "r"(dst), "l"(src));
}
__device__ __forceinline__ void mma_f16(float c[4], uint4 a, uint32_t b0, uint32_t b1) {
    asm volatile(
        "mma.sync.aligned.m16n8k16.row.col.f32.f16.f16.f32 "
        "{%0,%1,%2,%3}, {%4,%5,%6,%7}, {%8,%9}, {%0,%1,%2,%3};\n"
        : "+f"(c[0]), "+f"(c[1]), "+f"(c[2]), "+f"(c[3])
        : "r"(a.x), "r"(a.y), "r"(a.z), "r"(a.w), "r"(b0), "r"(b1));
}

// ---------------------------------------------------------------- small kernels
__global__ void k_detect_reset(const int* __restrict__ words) {
    // int64 tokens < 50000 -> all odd 32-bit words of first 128 elements are 0
    int v = words[threadIdx.x * 2 + 1];
    int any = __syncthreads_or(v != 0);
    if (threadIdx.x == 0) { g_tok64 = !any; g_cnt = 0; }
}

__device__ __forceinline__ int load_token(const int* __restrict__ t32, int p, int is64) {
    return is64 ? t32[2 * p] : t32[p];
}

__global__ void k_compact(const int* __restrict__ token, const int* __restrict__ need) {
    int p = blockIdx.x * blockDim.x + threadIdx.x;
    if (p < NTOK) {
        int t = load_token(token, p, g_tok64);
        if (t >= 0 && t < VOCAB && need[t]) {
            int pos = atomicAdd(&g_cnt, 1);
            g_list[pos] = p;
            g_tok[pos]  = t;
        }
    }
}

// Mega kernel: copy non-mapped rows | A fragment pack | W fragment pack.
__global__ void k_mega(const int* __restrict__ token, const int* __restrict__ need,
                       const float* __restrict__ emb, const float* __restrict__ W,
                       float4* __restrict__ out) {
    const int bid  = blockIdx.x;
    const int tid  = threadIdx.x;
    const int wid  = tid >> 5;
    const int lane = tid & 31;

    if (bid < NB_COPY) {
        // ---- copy branch: one warp per token row (6 indep float4 loads/lane)
        const int p = bid * 8 + wid;
        const int t = load_token(token, p, g_tok64);
        if (t < 0 || t >= VOCAB) return;
        if (need[t]) return;                         // GEMM writes these rows
        const float4* src = (const float4*)(emb + (size_t)t * DIM);
        float4* dst = out + (size_t)p * (DIM / 4);
        float4 v0 = src[lane];
        float4 v1 = src[lane + 32];
        float4 v2 = src[lane + 64];
        float4 v3 = src[lane + 96];
        float4 v4 = src[lane + 128];
        float4 v5 = src[lane + 160];
        dst[lane]       = v0;
        dst[lane + 32]  = v1;
        dst[lane + 64]  = v2;
        dst[lane + 96]  = v3;
        dst[lane + 128] = v4;
        dst[lane + 160] = v5;
    } else if (bid < NB_COPY + NB_PACK) {
        // ---- A pack branch: 8 warps = 2 m16-groups x 4 warps
        const int cnt = g_cnt;
        const int cnt_pad = (cnt + BM - 1) & ~(BM - 1);
        const int m16 = (bid - NB_COPY) * 2 + (wid >> 2);
        if (m16 * 16 >= cnt_pad) return;
        const int wg = wid & 3;                      // warp within group
        const int lr = lane >> 2, lk = lane & 3;
        const int r0 = m16 * 16 + lr, r1 = r0 + 8;
        const bool v0 = r0 < cnt, v1 = r1 < cnt;
        const float* e0 = emb + (size_t)(v0 ? g_tok[r0] : 0) * DIM;
        const float* e1 = emb + (size_t)(v1 ? g_tok[r1] : 0) * DIM;
        const float2 z2 = make_float2(0.f, 0.f);
        #pragma unroll
        for (int j = 0; j < NKS / 4; j += 2) {       // 12 ksteps, 2 at a time
            const int ksA = wg * (NKS / 4) + j;
            const int kA = ksA * 16 + lk * 2;
            const int kB = kA + 16;
            const float2 a0 = v0 ? *(const float2*)(e0 + kA)     : z2;
            const float2 a2 = v0 ? *(const float2*)(e0 + kA + 8) : z2;
            const float2 a1 = v1 ? *(const float2*)(e1 + kA)     : z2;
            const float2 a3 = v1 ? *(const float2*)(e1 + kA + 8) : z2;
            const float2 b0 = v0 ? *(const float2*)(e0 + kB)     : z2;
            const float2 b2 = v0 ? *(const float2*)(e0 + kB + 8) : z2;
            const float2 b1 = v1 ? *(const float2*)(e1 + kB)     : z2;
            const float2 b3 = v1 ? *(const float2*)(e1 + kB + 8) : z2;
            uint4 oA, oB;
            oA.x = f2h2(a0.x, a0.y); oA.y = f2h2(a1.x, a1.y);
            oA.z = f2h2(a2.x, a2.y); oA.w = f2h2(a3.x, a3.y);
            oB.x = f2h2(b0.x, b0.y); oB.y = f2h2(b1.x, b1.y);
            oB.z = f2h2(b2.x, b2.y); oB.w = f2h2(b3.x, b3.y);
            Ap[(size_t)(m16 * NKS + ksA) * 32 + lane]     = oA;
            Ap[(size_t)(m16 * NKS + ksA + 1) * 32 + lane] = oB;
        }
    } else {
        // ---- W pack branch
        const int gi = (bid - NB_COPY - NB_PACK) * 256 + tid;   // 48*48*32
        const int lane_w = gi & 31;
        const int ks   = (gi >> 5) % NKS;
        const int n16  = gi / (NKS * 32);
        const int na = n16 * 16 + (lane_w >> 2);
        const int nb = na + 8;
        const int k0 = ks * 16 + (lane_w & 3) * 2;
        uint4 o;
        o.x = f2h2(W[(size_t)k0 * DIM + na],       W[(size_t)(k0 + 1) * DIM + na]);
        o.y = f2h2(W[(size_t)(k0 + 8) * DIM + na], W[(size_t)(k0 + 9) * DIM + na]);
        o.z = f2h2(W[(size_t)k0 * DIM + nb],       W[(size_t)(k0 + 1) * DIM + nb]);
        o.w = f2h2(W[(size_t)(k0 + 8) * DIM + nb], W[(size_t)(k0 + 9) * DIM + nb]);
        Wp[(size_t)(n16 * NKS + ks) * 32 + lane_w] = o;
    }
}

// ---------------------------------------------------------------- GEMM
// Persistent CTAs; tile loop over (mtile, ntile) with ntile fastest (L2 A reuse).
// CTA 128x64, 8 warps 4Mx2N, warp tile 32x32. 2-stage cp.async, KCH=128, NCH=6.
__global__ __launch_bounds__(256, 2) void k_gemm(const float* __restrict__ bias,
                                                 float* __restrict__ out) {
    const int cnt = g_cnt;
    const int n_mt = (cnt + BM - 1) / BM;
    const int total_tiles = n_mt * NTILE_N;

    extern __shared__ uint32_t smem[];   // 2 stages x (A 32KB | B 16KB)

    const int tid  = threadIdx.x;
    const int lane = tid & 31;
    const int wid  = tid >> 5;
    const int wm   = wid >> 1;           // 0..3 (M)
    const int wn   = wid & 1;            // 0..1 (N)

    // Stage layout: A pieces (8 x 4KB), then B pieces (4 x 4KB); a piece is
    // one (m16|n16 group, 8 ksteps) = contiguous 4KB in Ap/Wp.
    #define ISSUE(c, s)                                                          \
    {                                                                            \
        const uint32_t dstA = smem_u32(smem) + (s) * STAGE_BYTES;                \
        const uint32_t dstB = dstA + A_STAGE_BYTES;                              \
        _Pragma("unroll")                                                        \
        for (int j = 0; j < 8; j++) {            /* A: 2048 x 16B */             \
            const int idx = tid + j * 256;                                       \
            const int piece = idx >> 8, off = idx & 255;                         \
            const uint4* src =                                                   \
                Ap + (size_t)((mtile * 8 + piece) * NKS + (c) * 8) * 32 + off;   \
            cp16(dstA + piece * 4096 + off * 16, src);                           \
        }                                                                        \
        _Pragma("unroll")                                                        \
        for (int j = 0; j < 4; j++) {            /* B: 1024 x 16B */             \
            const int idx = tid + j * 256;                                       \
            const int piece = idx >> 8, off = idx & 255;                         \
            const uint4* src =                                                   \
                Wp + (size_t)((n16_0 + piece) * NKS + (c) * 8) * 32 + off;       \
            cp16(dstB + piece * 4096 + off * 16, src);                           \
        }                                                                        \
        asm volatile("cp.async.commit_group;\n" ::: "memory");                   \
    }

    for (int tile = blockIdx.x; tile < total_tiles; tile += GEMM_GRID) {
        const int mtile = tile / NTILE_N;
        const int nt    = tile - mtile * NTILE_N;
        const int n16_0 = nt * (BN / 16);
        const int n0    = nt * BN;

        float acc[2][4][4];
        #pragma unroll
        for (int i = 0; i < 2; i++)
            #pragma unroll
            for (int j = 0; j < 4; j++)
                #pragma unroll
                for (int r = 0; r < 4; r++) acc[i][j][r] = 0.0f;

        ISSUE(0, 0)

        for (int c = 0; c < NCH; c++) {
            if (c + 1 < NCH) {
                ISSUE(c + 1, (c + 1) & 1)
                asm volatile("cp.async.wait_group 1;\n" ::: "memory");
            } else {
                asm volatile("cp.async.wait_group 0;\n" ::: "memory");
            }
            __syncthreads();   // chunk c data visible to all warps

            const uint32_t* aS = smem + (c & 1) * (STAGE_BYTES / 4);
            const uint32_t* bS = aS + (A_STAGE_BYTES / 4);
            #pragma unroll 2
            for (int ks = 0; ks < 8; ks++) {
                const uint4 a0 = *(const uint4*)(aS + ((wm * 2 + 0) * 1024 + ks * 128 + lane * 4));
                const uint4 a1 = *(const uint4*)(aS + ((wm * 2 + 1) * 1024 + ks * 128 + lane * 4));
                const uint4 b0 = *(const uint4*)(bS + ((wn * 2 + 0) * 1024 + ks * 128 + lane * 4));
                const uint4 b1 = *(const uint4*)(bS + ((wn * 2 + 1) * 1024 + ks * 128 + lane * 4));
                mma_f16(acc[0][0], a0, b0.x, b0.y);
                mma_f16(acc[0][1], a0, b0.z, b0.w);
                mma_f16(acc[0][2], a0, b1.x, b1.y);
                mma_f16(acc[0][3], a0, b1.z, b1.w);
                mma_f16(acc[1][0], a1, b0.x, b0.y);
                mma_f16(acc[1][1], a1, b0.z, b0.w);
                mma_f16(acc[1][2], a1, b1.x, b1.y);
                mma_f16(acc[1][3], a1, b1.z, b1.w);
            }
            __syncthreads();   // stage (c&1) free for reuse by ISSUE(c+2)
        }

        // epilogue: bias + scatter to out rows
        #pragma unroll
        for (int fm = 0; fm < 2; fm++) {
            const int r0 = mtile * BM + (wm * 2 + fm) * 16 + (lane >> 2);
            const int r1 = r0 + 8;
            #pragma unroll
            for (int fn = 0; fn < 4; fn++) {
                const int g = fn >> 1, sub = fn & 1;
                const int col = n0 + (wn * 2 + g) * 16 + sub * 8 + (lane & 3) * 2;
                const float b0 = bias[col], b1 = bias[col + 1];
                if (r0 < cnt) {
                    const int p = g_list[r0];
                    float2 v = make_float2(acc[0][0][0], 0.f);  // placeholder avoided
                    v = make_float2(acc[fm][fn][0] + b0, acc[fm][fn][1] + b1);
                    *(float2*)&out[(size_t)p * DIM + col] = v;
                }
                if (r1 < cnt) {
                    const int p = g_list[r1];
                    float2 v = make_float2(acc[fm][fn][2] + b0, acc[fm][fn][3] + b1);
                    *(float2*)&out[(size_t)p * DIM + col] = v;
                }
            }
        }
    }
    #undef ISSUE
}

// ---------------------------------------------------------------- launch
extern "C" void kernel_launch(void* const* d_in, const int* in_sizes, int n_in,
                              void* d_out, int out_size) {
    const int*   token = (const int*)d_in[0];   // int32 or int64 (auto-detected)
    const int*   need  = (const int*)d_in[1];
    const float* emb   = (const float*)d_in[2];
    const float* W     = (const float*)d_in[3];
    const float* bias  = (const float*)d_in[4];
    float*       out   = (float*)d_out;

    cudaFuncSetAttribute(k_gemm, cudaFuncAttributeMaxDynamicSharedMemorySize, GEMM_SMEM);

    k_detect_reset<<<1, 128>>>(token);
    k_compact<<<(NTOK + 255) / 256, 256>>>(token, need);
    k_mega<<<NB_TOTAL, 256>>>(token, need, emb, W, (float4*)out);
    k_gemm<<<GEMM_GRID, 256, GEMM_SMEM>>>(bias, out);
}

// round 11
// speedup vs baseline: 2.1364x; 1.0250x over previous
#include <cuda_runtime.h>
#include <cuda_fp16.h>
#include <cstdint>

#define VOCAB 50000
#define DIM   768
#define NTOK  16384
#define BM    128
#define BN    96
#define KCH   64                       // K per pipeline chunk (4 k16-steps)
#define NCH   (DIM / KCH)              // 12
#define NKS   (DIM / 16)               // 48 k16-steps per row
#define NM16  (NTOK / 16)              // 1024 fragment row-groups
#define NTILE_N (DIM / BN)             // 8
#define A_STAGE_BYTES (BM * KCH * 2)   // 16 KB (fp16)
#define B_STAGE_BYTES (BN * KCH * 2)   // 12 KB
#define STAGE_BYTES   (A_STAGE_BYTES + B_STAGE_BYTES)   // 28 KB
#define GEMM_SMEM     (2 * STAGE_BYTES)   // 56 KB -> 2 CTAs/SM
#define GEMM_GRID     296              // persistent: 2 CTAs/SM
#define GEMM_THREADS  192              // 6 warps: 2(M) x 3(N), warp tile 64x32

// mega-kernel block ranges
#define NB_COPY  (NTOK / 8)            // 2048: warp-per-row copy
#define NB_PACK  (NM16 / 2)            // 512:  2 m16-groups per block
#define NB_WPACK ((48 * NKS * 32) / 256)  // 288
#define NB_TOTAL (NB_COPY + NB_PACK + NB_WPACK)

__device__ int g_cnt;
__device__ int g_tok64;               // 1 if token buffer is int64
__device__ int g_list[NTOK];          // token position (output row)
__device__ int g_tok[NTOK];           // token id (embedding row)
// Fragment-packed fp16 operands for mma.sync m16n8k16 (row.col):
//   Ap[(m16*NKS + ks)*32 + lane] = uint4 {a0,a1,a2,a3}
//   Wp[(n16*NKS + ks)*32 + lane] = uint4 {b0@n,b1@n,b0@n+8,b1@n+8}
__device__ uint4 Ap[NM16 * NKS * 32];
__device__ uint4 Wp[(DIM / 16) * NKS * 32];

// ---------------------------------------------------------------- utilities
__device__ __forceinline__ uint32_t f2h2(float x, float y) {
    __half2 h = __floats2half2_rn(x, y);
    return *(uint32_t*)&h;
}
__device__ __forceinline__ uint32_t smem_u32(const void* p) {
    uint32_t a;
    asm("{ .reg .u64 t; cvta.to.shared.u64 t, %1; cvt.u32.u64 %0, t; }" : "=r"(a) : "l"(p));
    return a;
}
__device__ __forceinline__ void cp16(uint32_t dst, const void* src) {
    asm volatile("cp.async.cg.shared.global [%0], [%1], 16;\n" :: "r"(dst), "l"(src));
}
__device__ __forceinline__ void mma_f16(float c[4], uint4 a, uint32_t b0, uint32_t b1) {
    asm volatile(
        "mma.sync.aligned.m16n8k16.row.col.f32.f16.f16.f32 "
        "{%0,%1,%2,%3}, {%4,%5,%6,%7}, {%8,%9}, {%0,%1,%2,%3};\n"
        : "+f"(c[0]), "+f"(c[1]), "+f"(c[2]), "+f"(c[3])
        : "r"(a.x), "r"(a.y), "r"(a.z), "r"(a.w), "r"(b0), "r"(b1));
}

// ---------------------------------------------------------------- small kernels
__global__ void k_detect_reset(const int* __restrict__ words) {
    // int64 tokens < 50000 -> all odd 32-bit words of first 128 elements are 0
    int v = words[threadIdx.x * 2 + 1];
    int any = __syncthreads_or(v != 0);
    if (threadIdx.x == 0) { g_tok64 = !any; g_cnt = 0; }
}

__device__ __forceinline__ int load_token(const int* __restrict__ t32, int p, int is64) {
    return is64 ? t32[2 * p] : t32[p];
}

__global__ void k_compact(const int* __restrict__ token, const int* __restrict__ need) {
    int p = blockIdx.x * blockDim.x + threadIdx.x;
    if (p < NTOK) {
        int t = load_token(token, p, g_tok64);
        if (t >= 0 && t < VOCAB && need[t]) {
            int pos = atomicAdd(&g_cnt, 1);
            g_list[pos] = p;
            g_tok[pos]  = t;
        }
    }
}

// Mega kernel: copy non-mapped rows | A fragment pack | W fragment pack.
__global__ void k_mega(const int* __restrict__ token, const int* __restrict__ need,
                       const float* __restrict__ emb, const float* __restrict__ W,
                       float4* __restrict__ out) {
    const int bid  = blockIdx.x;
    const int tid  = threadIdx.x;
    const int wid  = tid >> 5;
    const int lane = tid & 31;

    if (bid < NB_COPY) {
        // ---- copy branch: one warp per token row (6 indep float4 loads/lane)
        const int p = bid * 8 + wid;
        const int t = load_token(token, p, g_tok64);
        if (t < 0 || t >= VOCAB) return;
        if (need[t]) return;                         // GEMM writes these rows
        const float4* src = (const float4*)(emb + (size_t)t * DIM);
        float4* dst = out + (size_t)p * (DIM / 4);
        float4 v0 = src[lane];
        float4 v1 = src[lane + 32];
        float4 v2 = src[lane + 64];
        float4 v3 = src[lane + 96];
        float4 v4 = src[lane + 128];
        float4 v5 = src[lane + 160];
        dst[lane]       = v0;
        dst[lane + 32]  = v1;
        dst[lane + 64]  = v2;
        dst[lane + 96]  = v3;
        dst[lane + 128] = v4;
        dst[lane + 160] = v5;
    } else if (bid < NB_COPY + NB_PACK) {
        // ---- A pack branch: 8 warps = 2 m16-groups x 4 warps
        const int cnt = g_cnt;
        const int cnt_pad = (cnt + BM - 1) & ~(BM - 1);
        const int m16 = (bid - NB_COPY) * 2 + (wid >> 2);
        if (m16 * 16 >= cnt_pad) return;
        const int wg = wid & 3;                      // warp within group
        const int lr = lane >> 2, lk = lane & 3;
        const int r0 = m16 * 16 + lr, r1 = r0 + 8;
        const bool v0 = r0 < cnt, v1 = r1 < cnt;
        const float* e0 = emb + (size_t)(v0 ? g_tok[r0] : 0) * DIM;
        const float* e1 = emb + (size_t)(v1 ? g_tok[r1] : 0) * DIM;
        const float2 z2 = make_float2(0.f, 0.f);
        #pragma unroll
        for (int j = 0; j < NKS / 4; j += 2) {       // 12 ksteps, 2 at a time
            const int ksA = wg * (NKS / 4) + j;
            const int kA = ksA * 16 + lk * 2;
            const int kB = kA + 16;
            const float2 a0 = v0 ? *(const float2*)(e0 + kA)     : z2;
            const float2 a2 = v0 ? *(const float2*)(e0 + kA + 8) : z2;
            const float2 a1 = v1 ? *(const float2*)(e1 + kA)     : z2;
            const float2 a3 = v1 ? *(const float2*)(e1 + kA + 8) : z2;
            const float2 b0 = v0 ? *(const float2*)(e0 + kB)     : z2;
            const float2 b2 = v0 ? *(const float2*)(e0 + kB + 8) : z2;
            const float2 b1 = v1 ? *(const float2*)(e1 + kB)     : z2;
            const float2 b3 = v1 ? *(const float2*)(e1 + kB + 8) : z2;
            uint4 oA, oB;
            oA.x = f2h2(a0.x, a0.y); oA.y = f2h2(a1.x, a1.y);
            oA.z = f2h2(a2.x, a2.y); oA.w = f2h2(a3.x, a3.y);
            oB.x = f2h2(b0.x, b0.y); oB.y = f2h2(b1.x, b1.y);
            oB.z = f2h2(b2.x, b2.y); oB.w = f2h2(b3.x, b3.y);
            Ap[(size_t)(m16 * NKS + ksA) * 32 + lane]     = oA;
            Ap[(size_t)(m16 * NKS + ksA + 1) * 32 + lane] = oB;
        }
    } else {
        // ---- W pack branch
        const int gi = (bid - NB_COPY - NB_PACK) * 256 + tid;   // 48*48*32
        const int lane_w = gi & 31;
        const int ks   = (gi >> 5) % NKS;
        const int n16  = gi / (NKS * 32);
        const int na = n16 * 16 + (lane_w >> 2);
        const int nb = na + 8;
        const int k0 = ks * 16 + (lane_w & 3) * 2;
        uint4 o;
        o.x = f2h2(W[(size_t)k0 * DIM + na],       W[(size_t)(k0 + 1) * DIM + na]);
        o.y = f2h2(W[(size_t)(k0 + 8) * DIM + na], W[(size_t)(k0 + 9) * DIM + na]);
        o.z = f2h2(W[(size_t)k0 * DIM + nb],       W[(size_t)(k0 + 1) * DIM + nb]);
        o.w = f2h2(W[(size_t)(k0 + 8) * DIM + nb], W[(size_t)(k0 + 9) * DIM + nb]);
        Wp[(size_t)(n16 * NKS + ks) * 32 + lane_w] = o;
    }
}

// ---------------------------------------------------------------- GEMM
// Persistent CTAs; tile loop (mtile, ntile), ntile fastest (L2 A reuse).
// CTA 128x96, 6 warps 2Mx3N, warp tile 64x32 (acc 64 regs, 192 B LDS/MMA).
// 2-stage cp.async, KCH=64, NCH=12.
__global__ __launch_bounds__(GEMM_THREADS, 2) void k_gemm(const float* __restrict__ bias,
                                                          float* __restrict__ out) {
    const int cnt = g_cnt;
    const int n_mt = (cnt + BM - 1) / BM;
    const int total_tiles = n_mt * NTILE_N;

    extern __shared__ uint32_t smem[];   // 2 stages x (A 16KB | B 12KB)

    const int tid  = threadIdx.x;
    const int lane = tid & 31;
    const int wid  = tid >> 5;           // 0..5
    const int wm   = wid >> 2;           // 0..1  (warps 0-3 -> m0, 4-5 -> m1? no)
    // 6 warps as 2M x 3N: wm = wid / 3, wn = wid % 3
    const int wm2  = wid / 3;            // 0..1 (M)
    const int wn   = wid - wm2 * 3;      // 0..2 (N)
    (void)wm;

    // Stage layout: A pieces (8 x 2KB m16-groups), then B pieces (6 x 2KB).
    #define ISSUE(c, s)                                                          \
    {                                                                            \
        const uint32_t dstA = smem_u32(smem) + (s) * STAGE_BYTES;                \
        const uint32_t dstB = dstA + A_STAGE_BYTES;                              \
        _Pragma("unroll")                                                        \
        for (int j = 0; j < 6; j++) {            /* A: 1024 x 16B */             \
            const int idx = tid + j * GEMM_THREADS;                              \
            if (idx < 1024) {                                                    \
                const int piece = idx >> 7, off = idx & 127;                     \
                const uint4* src =                                               \
                    Ap + (size_t)((mtile * 8 + piece) * NKS + (c) * 4) * 32 + off; \
                cp16(dstA + piece * 2048 + off * 16, src);                       \
            }                                                                    \
        }                                                                        \
        _Pragma("unroll")                                                        \
        for (int j = 0; j < 4; j++) {            /* B: 768 x 16B (exact) */      \
            const int idx = tid + j * GEMM_THREADS;                              \
            const int piece = idx >> 7, off = idx & 127;                         \
            const uint4* src =                                                   \
                Wp + (size_t)((n16_0 + piece) * NKS + (c) * 4) * 32 + off;       \
            cp16(dstB + piece * 2048 + off * 16, src);                           \
        }                                                                        \
        asm volatile("cp.async.commit_group;\n" ::: "memory");                   \
    }

    for (int tile = blockIdx.x; tile < total_tiles; tile += GEMM_GRID) {
        const int mtile = tile / NTILE_N;
        const int nt    = tile - mtile * NTILE_N;
        const int n16_0 = nt * (BN / 16);   // 6 n16 groups per tile
        const int n0    = nt * BN;

        float acc[4][4][4];                 // [fm 4 m16][fn 4 n8][frag 4]
        #pragma unroll
        for (int i = 0; i < 4; i++)
            #pragma unroll
            for (int j = 0; j < 4; j++)
                #pragma unroll
                for (int r = 0; r < 4; r++) acc[i][j][r] = 0.0f;

        ISSUE(0, 0)

        for (int c = 0; c < NCH; c++) {
            if (c + 1 < NCH) {
                ISSUE(c + 1, (c + 1) & 1)
                asm volatile("cp.async.wait_group 1;\n" ::: "memory");
            } else {
                asm volatile("cp.async.wait_group 0;\n" ::: "memory");
            }
            __syncthreads();   // chunk c data visible to all warps

            const uint32_t* aS = smem + (c & 1) * (STAGE_BYTES / 4);
            const uint32_t* bS = aS + (A_STAGE_BYTES / 4);
            #pragma unroll
            for (int ks = 0; ks < 4; ks++) {
                uint4 a[4], b[2];
                #pragma unroll
                for (int fm = 0; fm < 4; fm++)
                    a[fm] = *(const uint4*)(aS + ((wm2 * 4 + fm) * 512 + ks * 128 + lane * 4));
                #pragma unroll
                for (int g = 0; g < 2; g++)
                    b[g] = *(const uint4*)(bS + ((wn * 2 + g) * 512 + ks * 128 + lane * 4));
                #pragma unroll
                for (int fm = 0; fm < 4; fm++) {
                    mma_f16(acc[fm][0], a[fm], b[0].x, b[0].y);
                    mma_f16(acc[fm][1], a[fm], b[0].z, b[0].w);
                    mma_f16(acc[fm][2], a[fm], b[1].x, b[1].y);
                    mma_f16(acc[fm][3], a[fm], b[1].z, b[1].w);
                }
            }
            __syncthreads();   // stage (c&1) free for ISSUE(c+2)
        }

        // epilogue: bias + scatter to out rows
        #pragma unroll
        for (int fm = 0; fm < 4; fm++) {
            const int r0 = mtile * BM + wm2 * 64 + fm * 16 + (lane >> 2);
            const int r1 = r0 + 8;
            #pragma unroll
            for (int fn = 0; fn < 4; fn++) {
                const int g = fn >> 1, sub = fn & 1;
                const int col = n0 + (wn * 2 + g) * 16 + sub * 8 + (lane & 3) * 2;
                const float b0 = bias[col], b1 = bias[col + 1];
                if (r0 < cnt) {
                    const int p = g_list[r0];
                    float2 v = make_float2(acc[fm][fn][0] + b0, acc[fm][fn][1] + b1);
                    *(float2*)&out[(size_t)p * DIM + col] = v;
                }
                if (r1 < cnt) {
                    const int p = g_list[r1];
                    float2 v = make_float2(acc[fm][fn][2] + b0, acc[fm][fn][3] + b1);
                    *(float2*)&out[(size_t)p * DIM + col] = v;
                }
            }
        }
    }
    #undef ISSUE
}

// ---------------------------------------------------------------- launch
extern "C" void kernel_launch(void* const* d_in, const int* in_sizes, int n_in,
                              void* d_out, int out_size) {
    const int*   token = (const int*)d_in[0];   // int32 or int64 (auto-detected)
    const int*   need  = (const int*)d_in[1];
    const float* emb   = (const float*)d_in[2];
    const float* W     = (const float*)d_in[3];
    const float* bias  = (const float*)d_in[4];
    float*       out   = (float*)d_out;

    cudaFuncSetAttribute(k_gemm, cudaFuncAttributeMaxDynamicSharedMemorySize, GEMM_SMEM);

    k_detect_reset<<<1, 128>>>(token);
    k_compact<<<(NTOK + 255) / 256, 256>>>(token, need);
    k_mega<<<NB_TOTAL, 256>>>(token, need, emb, W, (float4*)out);
    k_gemm<<<GEMM_GRID, GEMM_THREADS, GEMM_SMEM>>>(bias, out);
}